// round 9
// baseline (speedup 1.0000x reference)
#include <cuda_runtime.h>
#include <math.h>

#define SS 128
#define POS_BANDS 10
#define D_ENC 63
#define D_VD 27
#define HID 64
#define FEAT 15

__device__ float g_dt;

// ---- weights in constant memory (uniform-const port, off the L1tex path) ----
__constant__ float W1c[D_ENC * HID];
__constant__ float b1c[HID];
__constant__ float W2c[HID * 16];
__constant__ float b2c[16];
__constant__ float V1c[FEAT * HID];    // rows 0..14 only
__constant__ float V2c[HID * 3];
__constant__ float c2c[3];

// ---------------- packed f32x2 FMA ----------------
struct F2 { union { float2 f; unsigned long long u; }; };
__device__ __forceinline__ F2 f2mk(float x, float y) { F2 r; r.f.x = x; r.f.y = y; return r; }
__device__ __forceinline__ F2 f2dup(float x) { return f2mk(x, x); }
__device__ __forceinline__ void fma2(F2& d, const F2 a, const F2 b) {
    asm("fma.rn.f32x2 %0, %1, %2, %0;" : "+l"(d.u) : "l"(a.u), "l"(b.u));
}

// ---------------------------------------------------------------------------
__global__ void reduce_dt_kernel(const float* __restrict__ tmin,
                                 const float* __restrict__ tmax, int n) {
    __shared__ float sh[256];
    float s = 0.f;
    for (int i = threadIdx.x; i < n; i += 256) s += tmax[i] - tmin[i];
    sh[threadIdx.x] = s;
    __syncthreads();
    for (int o = 128; o > 0; o >>= 1) {
        if (threadIdx.x < o) sh[threadIdx.x] += sh[threadIdx.x + o];
        __syncthreads();
    }
    if (threadIdx.x == 0) g_dt = sh[0] / (float)n / (float)SS;
}

// ---------------------------------------------------------------------------
struct __align__(16) SmemT {
    float bufA[64 * SS];   // 32 KB: ENC^T (rows 0..62) -> H^T (rows 0..63)
    float basev[64];       // c1 + vd_enc @ V1[15:42]
    float vd[28];
    float wagg[4];
    float red[16];
};

__global__ void __launch_bounds__(SS, 5)
raymarch_kernel(const float* __restrict__ orig, const float* __restrict__ dirs,
                const float* __restrict__ tmin, const float* __restrict__ tmax,
                const float* __restrict__ V1, const float* __restrict__ c1,
                float* __restrict__ out, int N) {
    extern __shared__ char smem_raw[];
    SmemT& sm = *reinterpret_cast<SmemT*>(smem_raw);
    const int r = blockIdx.x;
    const int tid = threadIdx.x;
    const int lane = tid & 31;
    const int warp = tid >> 5;
    const int s0 = lane * 4;        // layer-1 tile: 4 samples per lane
    const int col0 = warp * 16;     // layer-1 tile: 16 columns per warp (uniform)

    const float dx = dirs[r * 3 + 0], dy = dirs[r * 3 + 1], dz = dirs[r * 3 + 2];
    const float inv = 1.f / (sqrtf(dx * dx + dy * dy + dz * dz) + 1e-8f);
    if (tid < D_VD) {
        const int p = tid / 3, c = tid % 3;
        float v = ((c == 0) ? dx : (c == 1) ? dy : dz) * inv;
        float val;
        if (p == 0) val = v;
        else {
            const int band = (p - 1) >> 1;
            float sn, cs;
            sincosf(v * (float)(1 << band), &sn, &cs);
            val = ((p - 1) & 1) ? cs : sn;
        }
        sm.vd[tid] = val;
    }
    __syncthreads();

    // ---- base = c1 + vd_enc @ V1[15:42]  (per-ray constant; coalesced LDG) ----
    if (tid < HID) {
        float acc = c1[tid];
#pragma unroll
        for (int k = 0; k < D_VD; k++) acc += sm.vd[k] * V1[(FEAT + k) * HID + tid];
        sm.basev[tid] = acc;
    }

    // ---- positional encoding -> ENC^T in bufA rows 0..62 ----
    // Bands via angle-doubling: (c+is)^2 -> exactly doubles the angle.
    {
        const float t0 = tmin[r], t1 = tmax[r];
        const float tt = t0 + (float)tid * (1.f / (SS - 1)) * (t1 - t0);
        const float p3[3] = {orig[r * 3 + 0] + dx * tt,
                             orig[r * 3 + 1] + dy * tt,
                             orig[r * 3 + 2] + dz * tt};
#pragma unroll
        for (int c = 0; c < 3; c++) {
            const float pv = p3[c];
            sm.bufA[c * SS + tid] = pv;
            float s, cz;
            sincosf(pv, &s, &cz);          // band 0 (f = 1), precise
            sm.bufA[(3 + c) * SS + tid] = s;
            sm.bufA[(6 + c) * SS + tid] = cz;
#pragma unroll
            for (int b = 1; b < POS_BANDS; b++) {
                const float s2 = 2.f * s * cz;           // sin(2a) = 2 sin cos
                const float c2 = fmaf(-2.f * s, s, 1.f); // cos(2a) = 1 - 2 sin^2
                s = s2; cz = c2;
                sm.bufA[(3 + 6 * b + c) * SS + tid] = s;
                sm.bufA[(6 + 6 * b + c) * SS + tid] = cz;
            }
        }
    }
    __syncthreads();

    // ======== Layer 1: H^T = relu(W1^T @ ENC), warp-uniform weights ========
    {
        F2 acc[4][8];   // [sample][colpair]
#pragma unroll
        for (int cp = 0; cp < 8; cp++) {
            const F2 bb = f2mk(b1c[col0 + 2 * cp], b1c[col0 + 2 * cp + 1]);
#pragma unroll
            for (int s = 0; s < 4; s++) acc[s][cp] = bb;
        }
#pragma unroll 7
        for (int k = 0; k < D_ENC; k++) {
            const float4 av = *(const float4*)&sm.bufA[k * SS + s0];
            const float4 w0 = *(const float4*)&W1c[k * HID + col0];
            const float4 w1 = *(const float4*)&W1c[k * HID + col0 + 4];
            const float4 w2 = *(const float4*)&W1c[k * HID + col0 + 8];
            const float4 w3 = *(const float4*)&W1c[k * HID + col0 + 12];
            const F2 wp[8] = {f2mk(w0.x, w0.y), f2mk(w0.z, w0.w),
                              f2mk(w1.x, w1.y), f2mk(w1.z, w1.w),
                              f2mk(w2.x, w2.y), f2mk(w2.z, w2.w),
                              f2mk(w3.x, w3.y), f2mk(w3.z, w3.w)};
            const float as[4] = {av.x, av.y, av.z, av.w};
#pragma unroll
            for (int s = 0; s < 4; s++) {
                const F2 ad = f2dup(as[s]);
#pragma unroll
                for (int cp = 0; cp < 8; cp++) fma2(acc[s][cp], ad, wp[cp]);
            }
        }
        __syncthreads();   // all ENC reads done before overwriting bufA
#pragma unroll
        for (int cp = 0; cp < 8; cp++) {
            float4 v0, v1;
            v0.x = fmaxf(acc[0][cp].f.x, 0.f); v1.x = fmaxf(acc[0][cp].f.y, 0.f);
            v0.y = fmaxf(acc[1][cp].f.x, 0.f); v1.y = fmaxf(acc[1][cp].f.y, 0.f);
            v0.z = fmaxf(acc[2][cp].f.x, 0.f); v1.z = fmaxf(acc[2][cp].f.y, 0.f);
            v0.w = fmaxf(acc[3][cp].f.x, 0.f); v1.w = fmaxf(acc[3][cp].f.y, 0.f);
            *(float4*)&sm.bufA[(col0 + 2 * cp) * SS + s0] = v0;
            *(float4*)&sm.bufA[(col0 + 2 * cp + 1) * SS + s0] = v1;
        }
    }
    __syncthreads();

    // ======== Layers 2+3+4 register-resident, one sample per thread ========
    // ---- Layer 2: o[16] = W2^T @ h ----
    F2 o2[8];
#pragma unroll
    for (int cp = 0; cp < 8; cp++) o2[cp] = f2mk(b2c[2 * cp], b2c[2 * cp + 1]);
#pragma unroll 8
    for (int k = 0; k < HID; k++) {
        const F2 hd = f2dup(sm.bufA[k * SS + tid]);
#pragma unroll
        for (int q = 0; q < 4; q++) {
            const float4 w = *(const float4*)&W2c[k * 16 + 4 * q];
            fma2(o2[2 * q + 0], hd, f2mk(w.x, w.y));
            fma2(o2[2 * q + 1], hd, f2mk(w.z, w.w));
        }
    }

    // ---- extract sigma + rgb features; o2 dies here ----
    const float sigma = fmaxf(o2[0].f.x, 0.f);
    float fv[FEAT];
#pragma unroll
    for (int k = 0; k < FEAT; k++) {
        const int col = k + 1;
        fv[k] = (col & 1) ? o2[col >> 1].f.y : o2[col >> 1].f.x;
    }

    // ---- Layers 3+4 fused, chunked over 16 columns to cap live registers ----
    float r0 = c2c[0], r1 = c2c[1], r2 = c2c[2];
#pragma unroll
    for (int qc = 0; qc < 4; qc++) {
        const int base = qc * 16;
        F2 gch[8];
#pragma unroll
        for (int cp = 0; cp < 8; cp++)
            gch[cp] = f2mk(sm.basev[base + 2 * cp], sm.basev[base + 2 * cp + 1]);
#pragma unroll
        for (int k = 0; k < FEAT; k++) {
            const F2 ad = f2dup(fv[k]);
#pragma unroll
            for (int q = 0; q < 4; q++) {
                const float4 w = *(const float4*)&V1c[k * HID + base + 4 * q];
                fma2(gch[2 * q + 0], ad, f2mk(w.x, w.y));
                fma2(gch[2 * q + 1], ad, f2mk(w.z, w.w));
            }
        }
#pragma unroll
        for (int j = 0; j < 16; j++) {
            const int col = base + j;
            const float gv = fmaxf((j & 1) ? gch[j >> 1].f.y : gch[j >> 1].f.x, 0.f);
            r0 += gv * V2c[col * 3 + 0];
            r1 += gv * V2c[col * 3 + 1];
            r2 += gv * V2c[col * 3 + 2];
        }
    }
    r0 = 1.f / (1.f + __expf(-r0));
    r1 = 1.f / (1.f + __expf(-r1));
    r2 = 1.f / (1.f + __expf(-r2));

    // ---- compositing ----
    {
        const float dtv = g_dt;
        const float om = __expf(-sigma * dtv);
        const float alpha = 1.f - om;

        // warp-level exclusive product scan
        float e = __shfl_up_sync(0xffffffffu, om, 1);
        if (lane == 0) e = 1.f;
        float x = e;
#pragma unroll
        for (int off = 1; off < 32; off <<= 1) {
            const float v = __shfl_up_sync(0xffffffffu, x, off);
            if (lane >= off) x *= v;
        }
        if (lane == 31) sm.wagg[warp] = x * om;
        __syncthreads();
        float pre = 1.f;
#pragma unroll
        for (int w2 = 0; w2 < 4; w2++)
            if (w2 < warp) pre *= sm.wagg[w2];
        const float Texcl = pre * x;

        const bool active = (Texcl > 1e-4f);
        const float w = active ? Texcl * alpha : 0.f;

        float cr = w * r0, cg2 = w * r1, cb = w * r2;
        float tf = active ? om : 1.f;
#pragma unroll
        for (int off = 16; off; off >>= 1) {
            cr  += __shfl_down_sync(0xffffffffu, cr,  off);
            cg2 += __shfl_down_sync(0xffffffffu, cg2, off);
            cb  += __shfl_down_sync(0xffffffffu, cb,  off);
            tf  *= __shfl_down_sync(0xffffffffu, tf,  off);
        }
        if (lane == 0) {
            sm.red[warp * 4 + 0] = cr;
            sm.red[warp * 4 + 1] = cg2;
            sm.red[warp * 4 + 2] = cb;
            sm.red[warp * 4 + 3] = tf;
        }
        __syncthreads();
        if (tid == 0) {
            out[r * 3 + 0] = sm.red[0] + sm.red[4] + sm.red[8] + sm.red[12];
            out[r * 3 + 1] = sm.red[1] + sm.red[5] + sm.red[9] + sm.red[13];
            out[r * 3 + 2] = sm.red[2] + sm.red[6] + sm.red[10] + sm.red[14];
            out[3 * N + r] = sm.red[3] * sm.red[7] * sm.red[11] * sm.red[15];
        }
    }
}

// ---------------------------------------------------------------------------
extern "C" void kernel_launch(void* const* d_in, const int* in_sizes, int n_in,
                              void* d_out, int out_size) {
    const float* orig = (const float*)d_in[0];
    const float* dirs = (const float*)d_in[1];
    const float* tmin = (const float*)d_in[2];
    const float* tmax = (const float*)d_in[3];
    const float* W1   = (const float*)d_in[4];
    const float* b1   = (const float*)d_in[5];
    const float* W2   = (const float*)d_in[6];
    const float* b2   = (const float*)d_in[7];
    const float* V1   = (const float*)d_in[8];
    const float* c1   = (const float*)d_in[9];
    const float* V2   = (const float*)d_in[10];
    const float* c2   = (const float*)d_in[11];
    float* out = (float*)d_out;
    const int N = in_sizes[2];

    cudaMemcpyToSymbolAsync(W1c, W1, D_ENC * HID * sizeof(float), 0, cudaMemcpyDeviceToDevice, 0);
    cudaMemcpyToSymbolAsync(b1c, b1, HID * sizeof(float), 0, cudaMemcpyDeviceToDevice, 0);
    cudaMemcpyToSymbolAsync(W2c, W2, HID * 16 * sizeof(float), 0, cudaMemcpyDeviceToDevice, 0);
    cudaMemcpyToSymbolAsync(b2c, b2, 16 * sizeof(float), 0, cudaMemcpyDeviceToDevice, 0);
    cudaMemcpyToSymbolAsync(V1c, V1, FEAT * HID * sizeof(float), 0, cudaMemcpyDeviceToDevice, 0);
    cudaMemcpyToSymbolAsync(V2c, V2, HID * 3 * sizeof(float), 0, cudaMemcpyDeviceToDevice, 0);
    cudaMemcpyToSymbolAsync(c2c, c2, 3 * sizeof(float), 0, cudaMemcpyDeviceToDevice, 0);

    reduce_dt_kernel<<<1, 256>>>(tmin, tmax, N);
    raymarch_kernel<<<N, SS, sizeof(SmemT)>>>(orig, dirs, tmin, tmax,
                                              V1, c1, out, N);
}